// round 1
// baseline (speedup 1.0000x reference)
#include <cuda_runtime.h>
#include <math.h>

// ---------------- problem constants ----------------
#define NGRAPH 64
#define NPER   1024
#define NNODES (NGRAPH*NPER)     // 65536
#define KKEEP  820
#define NPOOL  (NGRAPH*KKEEP)    // 52480
#define NE     524288
#define HD     128               // F == H == 128

// ---------------- device scratch (no allocations allowed) ----------------
__device__ float g_agg[NNODES*HD];
__device__ float g_x1 [NNODES*HD];   // also reused as x3 buffer
__device__ float g_x2 [NNODES*HD];
__device__ float g_xp [NPOOL*HD];
__device__ int   g_cnt    [NNODES];
__device__ int   g_rowptr [NNODES+1];
__device__ int   g_cursor [NNODES];
__device__ int   g_csr    [NE];
__device__ int   g_cnt2   [NPOOL];
__device__ int   g_rowptr2[NPOOL+1];
__device__ int   g_cursor2[NPOOL];
__device__ int   g_csr2   [NE];
__device__ int   g_ns     [NE];
__device__ int   g_nd     [NE];
__device__ int   g_map    [NNODES];
__device__ int   g_old    [NPOOL];
__device__ float g_val    [NPOOL];
__device__ float g_score  [NNODES];
__device__ float g_cat    [NGRAPH*384];

// ---------------- tiny utility kernels ----------------
__global__ void zero_int_kernel(int* p, int n) {
    int i = blockIdx.x*blockDim.x + threadIdx.x;
    if (i < n) p[i] = 0;
}
__global__ void copy_int_kernel(const int* __restrict__ a, int* __restrict__ b, int n) {
    int i = blockIdx.x*blockDim.x + threadIdx.x;
    if (i < n) b[i] = a[i];
}

// histogram of dst
__global__ void hist_kernel(const int* __restrict__ dst, int* cnt, int n) {
    int i = blockIdx.x*blockDim.x + threadIdx.x;
    if (i < n) atomicAdd(&cnt[dst[i]], 1);
}

// single-block exclusive scan: rowptr[0]=0, rowptr[i+1]=sum(cnt[0..i])
__global__ void scan_kernel(const int* __restrict__ cnt, int* __restrict__ rowptr, int n) {
    __shared__ int s[1024];
    __shared__ int carry_s;
    int t = threadIdx.x;
    if (t == 0) carry_s = 0;
    __syncthreads();
    for (int base = 0; base < n; base += 1024) {
        int i = base + t;
        int v = (i < n) ? cnt[i] : 0;
        s[t] = v; __syncthreads();
        for (int off = 1; off < 1024; off <<= 1) {
            int add = (t >= off) ? s[t-off] : 0;
            __syncthreads();
            s[t] += add;
            __syncthreads();
        }
        int carry = carry_s;
        if (i < n) rowptr[i+1] = carry + s[t];
        __syncthreads();
        if (t == 0) carry_s = carry + s[1023];
        __syncthreads();
    }
    if (t == 0) rowptr[0] = 0;
}

// scatter edges into CSR slots (by dst)
__global__ void scatter_kernel(const int* __restrict__ src, const int* __restrict__ dst,
                               int* cursor, int* __restrict__ csr, int n) {
    int i = blockIdx.x*blockDim.x + threadIdx.x;
    if (i < n) {
        int pos = atomicAdd(&cursor[dst[i]], 1);
        csr[pos] = src[i];
    }
}

// ---------------- mean aggregation: warp per destination node ----------------
__global__ void aggregate_kernel(const float* __restrict__ x, const int* __restrict__ rowptr,
                                 const int* __restrict__ csr, float* __restrict__ agg, int n) {
    int warp = (blockIdx.x*blockDim.x + threadIdx.x) >> 5;
    int lane = threadIdx.x & 31;
    if (warp >= n) return;
    int beg = rowptr[warp], end = rowptr[warp+1];
    float4 acc = make_float4(0.f, 0.f, 0.f, 0.f);
    const float4* x4 = (const float4*)x;
    for (int e = beg; e < end; e++) {
        int s = csr[e];
        float4 v = x4[s*32 + lane];
        acc.x += v.x; acc.y += v.y; acc.z += v.z; acc.w += v.w;
    }
    float inv = (end > beg) ? 1.f/(float)(end-beg) : 0.f;
    acc.x *= inv; acc.y *= inv; acc.z *= inv; acc.w *= inv;
    ((float4*)agg)[warp*32 + lane] = acc;
}

// ---------------- fused GraphConv GEMM ----------------
// out[m,n] = relu( sum_k A1[m,k]*W1[n,k] + sum_k A2[m,k]*W2[n,k] + bias[n] )
// BM=128, BN=128(full), BK=16, 256 threads, 8x8 register tile per thread.
__global__ void __launch_bounds__(256)
conv_gemm_kernel(const float* __restrict__ A1, const float* __restrict__ A2,
                 const float* __restrict__ W1, const float* __restrict__ W2,
                 const float* __restrict__ bias, float* __restrict__ out) {
    __shared__ float As[16][128];
    __shared__ float Bs[16][128];
    int tid = threadIdx.x;
    int m0  = blockIdx.x * 128;
    int tm = (tid >> 4) * 8;     // 0..120
    int tn = (tid & 15) * 8;     // 0..120
    float acc[8][8];
    #pragma unroll
    for (int i = 0; i < 8; i++)
        #pragma unroll
        for (int j = 0; j < 8; j++) acc[i][j] = 0.f;

    #pragma unroll 1
    for (int phase = 0; phase < 2; phase++) {
        const float* A = phase ? A2 : A1;
        const float* W = phase ? W2 : W1;
        #pragma unroll 1
        for (int kc = 0; kc < 128; kc += 16) {
            // load A tile 128x16 -> As[k][m]
            {
                int r  = tid >> 2;        // 0..63
                int c4 = (tid & 3) * 4;   // 0,4,8,12
                #pragma unroll
                for (int rr = 0; rr < 128; rr += 64) {
                    float4 v = *(const float4*)&A[(size_t)(m0 + r + rr)*HD + kc + c4];
                    As[c4+0][r+rr] = v.x; As[c4+1][r+rr] = v.y;
                    As[c4+2][r+rr] = v.z; As[c4+3][r+rr] = v.w;
                }
            }
            // load W tile 128x16 -> Bs[k][n]
            {
                #pragma unroll
                for (int it = 0; it < 2; it++) {
                    int idx = tid*2 + it;
                    int n = idx >> 2;
                    int c = (idx & 3) * 4;
                    float4 v = *(const float4*)&W[(size_t)n*HD + kc + c];
                    Bs[c+0][n] = v.x; Bs[c+1][n] = v.y;
                    Bs[c+2][n] = v.z; Bs[c+3][n] = v.w;
                }
            }
            __syncthreads();
            #pragma unroll
            for (int k = 0; k < 16; k++) {
                float a[8], b[8];
                #pragma unroll
                for (int i = 0; i < 8; i++) a[i] = As[k][tm+i];
                #pragma unroll
                for (int j = 0; j < 8; j++) b[j] = Bs[k][tn+j];
                #pragma unroll
                for (int i = 0; i < 8; i++)
                    #pragma unroll
                    for (int j = 0; j < 8; j++) acc[i][j] += a[i]*b[j];
            }
            __syncthreads();
        }
    }
    // epilogue: bias + relu
    #pragma unroll
    for (int i = 0; i < 8; i++) {
        #pragma unroll
        for (int j = 0; j < 8; j++) {
            float v = acc[i][j] + bias[tn+j];
            out[(size_t)(m0 + tm + i)*HD + tn + j] = fmaxf(v, 0.f);
        }
    }
}

// ---------------- global mean pool into concat buffer ----------------
__global__ void meanpool_kernel(const float* __restrict__ x, float* __restrict__ cat,
                                int nodes, int off, float inv) {
    int g = blockIdx.x;
    int t = threadIdx.x;          // 512 threads
    int f = t & 127;
    int part = t >> 7;            // 0..3
    float acc = 0.f;
    size_t base = (size_t)g * nodes * HD;
    for (int i = part; i < nodes; i += 4)
        acc += x[base + (size_t)i*HD + f];
    __shared__ float s[512];
    s[t] = acc;
    __syncthreads();
    if (part == 0)
        cat[g*384 + off + f] = (s[f] + s[128+f] + s[256+f] + s[384+f]) * inv;
}

// ---------------- TopK scoring: warp per node ----------------
__global__ void score_kernel(const float* __restrict__ x, const float* __restrict__ pw,
                             float* __restrict__ score, int n) {
    int warp = (blockIdx.x*blockDim.x + threadIdx.x) >> 5;
    int lane = threadIdx.x & 31;
    if (warp >= n) return;
    float4 v = ((const float4*)x)[warp*32 + lane];
    float4 p = ((const float4*)pw)[lane];
    float d  = v.x*p.x + v.y*p.y + v.z*p.z + v.w*p.w;
    float pp = p.x*p.x + p.y*p.y + p.z*p.z + p.w*p.w;
    #pragma unroll
    for (int o = 16; o; o >>= 1) {
        d  += __shfl_xor_sync(0xFFFFFFFFu, d,  o);
        pp += __shfl_xor_sync(0xFFFFFFFFu, pp, o);
    }
    if (lane == 0) score[warp] = tanhf(d / sqrtf(pp));
}

// ---------------- TopK selection: one block per graph, bitonic sort 1024 ----------------
__global__ void topk_kernel(const float* __restrict__ score, int* __restrict__ map,
                            int* __restrict__ oldidx, float* __restrict__ val) {
    int g = blockIdx.x, t = threadIdx.x;   // 1024 threads
    __shared__ float sk[1024];
    __shared__ int   si[1024];
    map[g*NPER + t] = -1;
    sk[t] = score[g*NPER + t];
    si[t] = t;
    __syncthreads();
    for (int k = 2; k <= 1024; k <<= 1) {
        for (int j = k >> 1; j > 0; j >>= 1) {
            int ixj = t ^ j;
            if (ixj > t) {
                bool desc = ((t & k) == 0);
                float a = sk[t], b = sk[ixj];
                bool sw = desc ? (a < b) : (a > b);
                if (sw) {
                    sk[t] = b; sk[ixj] = a;
                    int tmp = si[t]; si[t] = si[ixj]; si[ixj] = tmp;
                }
            }
            __syncthreads();
        }
    }
    if (t < KKEEP) {
        int old = g*NPER + si[t];
        int nw  = g*KKEEP + t;
        map[old]   = nw;
        oldidx[nw] = old;
        val[nw]    = sk[t];
    }
}

// gather kept nodes, scale by score
__global__ void gather_scale_kernel(const float* __restrict__ x, const int* __restrict__ oldidx,
                                    const float* __restrict__ val, float* __restrict__ xp) {
    int warp = (blockIdx.x*blockDim.x + threadIdx.x) >> 5;
    int lane = threadIdx.x & 31;
    if (warp >= NPOOL) return;
    int old = oldidx[warp];
    float v = val[warp];
    float4 r = ((const float4*)x)[old*32 + lane];
    r.x *= v; r.y *= v; r.z *= v; r.w *= v;
    ((float4*)xp)[warp*32 + lane] = r;
}

// relabel edges through map, histogram valid edges by new dst
__global__ void filter_kernel(const int* __restrict__ src, const int* __restrict__ dst,
                              const int* __restrict__ map, int* __restrict__ ns,
                              int* __restrict__ nd, int* cnt2, int n) {
    int i = blockIdx.x*blockDim.x + threadIdx.x;
    if (i >= n) return;
    int a = map[src[i]];
    int b = map[dst[i]];
    if (a >= 0 && b >= 0) {
        ns[i] = a; nd[i] = b;
        atomicAdd(&cnt2[b], 1);
    } else {
        ns[i] = -1; nd[i] = 0;
    }
}

__global__ void scatter2_kernel(const int* __restrict__ ns, const int* __restrict__ nd,
                                int* cursor, int* __restrict__ csr, int n) {
    int i = blockIdx.x*blockDim.x + threadIdx.x;
    if (i < n && ns[i] >= 0) {
        int pos = atomicAdd(&cursor[nd[i]], 1);
        csr[pos] = ns[i];
    }
}

// ---------------- MLP head + log_softmax: one block per graph ----------------
__global__ void head_kernel(const float* __restrict__ cat, const float* __restrict__ W1,
                            const float* __restrict__ b1, const float* __restrict__ W2,
                            const float* __restrict__ b2, float* __restrict__ out) {
    int g = blockIdx.x, t = threadIdx.x;   // 128 threads
    __shared__ float sc[384];
    __shared__ float sh[128];
    __shared__ float sl[10];
    for (int i = t; i < 384; i += 128) sc[i] = cat[g*384 + i];
    __syncthreads();
    float acc = b1[t];
    #pragma unroll 4
    for (int k = 0; k < 384; k++) acc += sc[k] * W1[t*384 + k];
    sh[t] = fmaxf(acc, 0.f);
    __syncthreads();
    if (t < 10) {
        float a = b2[t];
        #pragma unroll 4
        for (int f = 0; f < 128; f++) a += sh[f] * W2[t*128 + f];
        sl[t] = a;
    }
    __syncthreads();
    if (t == 0) {
        float mx = sl[0];
        #pragma unroll
        for (int c = 1; c < 10; c++) mx = fmaxf(mx, sl[c]);
        float s = 0.f;
        #pragma unroll
        for (int c = 0; c < 10; c++) s += expf(sl[c] - mx);
        float lse = mx + logf(s);
        #pragma unroll
        for (int c = 0; c < 10; c++) out[g*10 + c] = sl[c] - lse;
    }
}

// ---------------- launch ----------------
extern "C" void kernel_launch(void* const* d_in, const int* in_sizes, int n_in,
                              void* d_out, int out_size) {
    const float* x       = (const float*)d_in[0];
    const int*   ei      = (const int*)  d_in[1];
    const int*   src     = ei;
    const int*   dst     = ei + NE;
    const float* W_rel1  = (const float*)d_in[3];
    const float* b_rel1  = (const float*)d_in[4];
    const float* W_root1 = (const float*)d_in[5];
    const float* W_rel2  = (const float*)d_in[6];
    const float* b_rel2  = (const float*)d_in[7];
    const float* W_root2 = (const float*)d_in[8];
    const float* W_rel3  = (const float*)d_in[9];
    const float* b_rel3  = (const float*)d_in[10];
    const float* W_root3 = (const float*)d_in[11];
    const float* p_w     = (const float*)d_in[12];
    const float* W_l1    = (const float*)d_in[13];
    const float* b_l1    = (const float*)d_in[14];
    const float* W_l2    = (const float*)d_in[15];
    const float* b_l2    = (const float*)d_in[16];
    float* out = (float*)d_out;

    float *agg, *x1, *x2, *xp, *val, *score, *cat;
    int *cnt, *rowptr, *cursor, *csr, *cnt2, *rowptr2, *cursor2, *csr2;
    int *ns, *nd, *map, *old;
    cudaGetSymbolAddress((void**)&agg,     g_agg);
    cudaGetSymbolAddress((void**)&x1,      g_x1);
    cudaGetSymbolAddress((void**)&x2,      g_x2);
    cudaGetSymbolAddress((void**)&xp,      g_xp);
    cudaGetSymbolAddress((void**)&cnt,     g_cnt);
    cudaGetSymbolAddress((void**)&rowptr,  g_rowptr);
    cudaGetSymbolAddress((void**)&cursor,  g_cursor);
    cudaGetSymbolAddress((void**)&csr,     g_csr);
    cudaGetSymbolAddress((void**)&cnt2,    g_cnt2);
    cudaGetSymbolAddress((void**)&rowptr2, g_rowptr2);
    cudaGetSymbolAddress((void**)&cursor2, g_cursor2);
    cudaGetSymbolAddress((void**)&csr2,    g_csr2);
    cudaGetSymbolAddress((void**)&ns,      g_ns);
    cudaGetSymbolAddress((void**)&nd,      g_nd);
    cudaGetSymbolAddress((void**)&map,     g_map);
    cudaGetSymbolAddress((void**)&old,     g_old);
    cudaGetSymbolAddress((void**)&val,     g_val);
    cudaGetSymbolAddress((void**)&score,   g_score);
    cudaGetSymbolAddress((void**)&cat,     g_cat);

    const int T = 256;
    // ---- CSR of original graph (by dst) ----
    zero_int_kernel<<<(NNODES+T-1)/T, T>>>(cnt, NNODES);
    hist_kernel<<<(NE+T-1)/T, T>>>(dst, cnt, NE);
    scan_kernel<<<1, 1024>>>(cnt, rowptr, NNODES);
    copy_int_kernel<<<(NNODES+T-1)/T, T>>>(rowptr, cursor, NNODES);
    scatter_kernel<<<(NE+T-1)/T, T>>>(src, dst, cursor, csr, NE);

    // ---- conv1 ----
    aggregate_kernel<<<NNODES/8, T>>>(x, rowptr, csr, agg, NNODES);
    conv_gemm_kernel<<<NNODES/128, 256>>>(agg, x, W_rel1, W_root1, b_rel1, x1);
    meanpool_kernel<<<NGRAPH, 512>>>(x1, cat, NPER, 0, 1.f/(float)NPER);

    // ---- conv2 ----
    aggregate_kernel<<<NNODES/8, T>>>(x1, rowptr, csr, agg, NNODES);
    conv_gemm_kernel<<<NNODES/128, 256>>>(agg, x1, W_rel2, W_root2, b_rel2, x2);
    meanpool_kernel<<<NGRAPH, 512>>>(x2, cat, NPER, 128, 1.f/(float)NPER);

    // ---- TopK pooling ----
    score_kernel<<<NNODES/8, T>>>(x2, p_w, score, NNODES);
    topk_kernel<<<NGRAPH, 1024>>>(score, map, old, val);
    gather_scale_kernel<<<NPOOL/8, T>>>(x2, old, val, xp);

    // ---- CSR of pooled graph ----
    zero_int_kernel<<<(NPOOL+T-1)/T, T>>>(cnt2, NPOOL);
    filter_kernel<<<(NE+T-1)/T, T>>>(src, dst, map, ns, nd, cnt2, NE);
    scan_kernel<<<1, 1024>>>(cnt2, rowptr2, NPOOL);
    copy_int_kernel<<<(NPOOL+T-1)/T, T>>>(rowptr2, cursor2, NPOOL);
    scatter2_kernel<<<(NE+T-1)/T, T>>>(ns, nd, cursor2, csr2, NE);

    // ---- conv3 (reuse x1 buffer as x3) ----
    aggregate_kernel<<<NPOOL/8, T>>>(xp, rowptr2, csr2, agg, NPOOL);
    conv_gemm_kernel<<<NPOOL/128, 256>>>(agg, xp, W_rel3, W_root3, b_rel3, x1);
    meanpool_kernel<<<NGRAPH, 512>>>(x1, cat, KKEEP, 256, 1.f/(float)KKEEP);

    // ---- head ----
    head_kernel<<<NGRAPH, 128>>>(cat, W_l1, b_l1, W_l2, b_l2, out);
}

// round 5
// speedup vs baseline: 1.8580x; 1.8580x over previous
#include <cuda_runtime.h>
#include <cuda_bf16.h>
#include <math.h>
#include <stdint.h>

// ---------------- problem constants ----------------
#define NGRAPH 64
#define NPER   1024
#define NNODES (NGRAPH*NPER)     // 65536
#define KKEEP  820
#define NPOOL  (NGRAPH*KKEEP)    // 52480
#define NE     524288
#define HD     128               // F == H == 128

// ---------------- device scratch (no allocations allowed) ----------------
__device__ float g_agg[NNODES*HD];
__device__ float g_x1 [NNODES*HD];   // also reused as x3 buffer
__device__ float g_x2 [NNODES*HD];
__device__ float g_xp [NPOOL*HD];
__device__ int   g_cnt    [NNODES];
__device__ int   g_rowptr [NNODES+1];
__device__ int   g_cursor [NNODES+1];
__device__ int   g_csr    [NE];
__device__ int   g_cnt2   [NPOOL];
__device__ int   g_rowptr2[NPOOL+1];
__device__ int   g_cursor2[NPOOL+1];
__device__ int   g_csr2   [NE];
__device__ int   g_ns     [NE];
__device__ int   g_nd     [NE];
__device__ int   g_map    [NNODES];
__device__ int   g_old    [NPOOL];
__device__ float g_val    [NPOOL];
__device__ float g_score  [NNODES];
__device__ float g_cat    [NGRAPH*384];
__device__ int   g_bsum   [64];

// ---------------- tiny utility kernels ----------------
__global__ void zero_int_kernel(int* p, int n) {
    int i = blockIdx.x*blockDim.x + threadIdx.x;
    if (i < n) p[i] = 0;
}

// histogram of dst
__global__ void hist_kernel(const int* __restrict__ dst, int* cnt, int n) {
    int i = blockIdx.x*blockDim.x + threadIdx.x;
    if (i < n) atomicAdd(&cnt[dst[i]], 1);
}

// ---- hierarchical scan (3 kernels) ----
__global__ void scan_local_kernel(const int* __restrict__ cnt, int* __restrict__ rowptr,
                                  int* __restrict__ bsum, int n) {
    __shared__ int s[1024];
    int t = threadIdx.x;
    int i = blockIdx.x*1024 + t;
    int v = (i < n) ? cnt[i] : 0;
    s[t] = v; __syncthreads();
    for (int off = 1; off < 1024; off <<= 1) {
        int add = (t >= off) ? s[t-off] : 0;
        __syncthreads();
        s[t] += add;
        __syncthreads();
    }
    if (i < n) rowptr[i+1] = s[t];   // inclusive, no block offset yet
    if (t == 1023) bsum[blockIdx.x] = s[1023];
}
__global__ void scan_bsum_kernel(int* bsum, int nb, int* rowptr, int* cursor) {
    __shared__ int s[64];
    int t = threadIdx.x;   // 64 threads
    s[t] = (t < nb) ? bsum[t] : 0;
    __syncthreads();
    for (int off = 1; off < 64; off <<= 1) {
        int a = (t >= off) ? s[t-off] : 0;
        __syncthreads();
        s[t] += a;
        __syncthreads();
    }
    if (t < nb) bsum[t] = s[t];   // inclusive block sums
    if (t == 0) { rowptr[0] = 0; cursor[0] = 0; }
}
__global__ void scan_add_kernel(int* __restrict__ rowptr, const int* __restrict__ bsum,
                                int* __restrict__ cursor, int n) {
    int i = blockIdx.x*blockDim.x + threadIdx.x;
    if (i >= n) return;
    int b = i >> 10;
    int v = rowptr[i+1] + ((b > 0) ? bsum[b-1] : 0);
    rowptr[i+1] = v;
    cursor[i+1] = v;
}

// scatter edges into CSR slots (by dst)
__global__ void scatter_kernel(const int* __restrict__ src, const int* __restrict__ dst,
                               int* cursor, int* __restrict__ csr, int n) {
    int i = blockIdx.x*blockDim.x + threadIdx.x;
    if (i < n) {
        int pos = atomicAdd(&cursor[dst[i]], 1);
        csr[pos] = src[i];
    }
}

// ---------------- mean aggregation: warp per destination node ----------------
__global__ void aggregate_kernel(const float* __restrict__ x, const int* __restrict__ rowptr,
                                 const int* __restrict__ csr, float* __restrict__ agg, int n) {
    int warp = (blockIdx.x*blockDim.x + threadIdx.x) >> 5;
    int lane = threadIdx.x & 31;
    if (warp >= n) return;
    int beg = rowptr[warp], end = rowptr[warp+1];
    float4 acc = make_float4(0.f, 0.f, 0.f, 0.f);
    const float4* x4 = (const float4*)x;
    for (int e = beg; e < end; e++) {
        int s = csr[e];
        float4 v = x4[s*32 + lane];
        acc.x += v.x; acc.y += v.y; acc.z += v.z; acc.w += v.w;
    }
    float inv = (end > beg) ? 1.f/(float)(end-beg) : 0.f;
    acc.x *= inv; acc.y *= inv; acc.z *= inv; acc.w *= inv;
    ((float4*)agg)[warp*32 + lane] = acc;
}

// =======================================================================
//        bf16x3 mma.sync fused GraphConv GEMM (plain sm_100 path)
//  out[m,n] = relu( A1[m,:]·W1[n,:] + A2[m,:]·W2[n,:] + bias[n] )
//  BM=128, BN=128, K=256 total (2 phases x 2 chunks of 64)
//  fp32 = bf16_hi + bf16_lo; C += Ah·Bh + Ah·Bl + Al·Bh (fp32 accum)
//  NOTE: B (=W) is stored [n][k] k-contiguous, same as A -> NON-trans ldmatrix.
// =======================================================================

#define KC       64              // k-chunk
#define SSTRIDE  72              // bf16 elements per smem row (64 + 8 pad)
#define TILE_B   (128*SSTRIDE*2) // 18432 bytes per matrix
#define CONV_SMEM (4*TILE_B)     // Ah, Al, Bh, Bl = 73728 bytes

__device__ __forceinline__ void ldsm4(uint32_t* r, uint32_t addr) {
    asm volatile("ldmatrix.sync.aligned.m8n8.x4.shared.b16 {%0,%1,%2,%3}, [%4];"
                 : "=r"(r[0]), "=r"(r[1]), "=r"(r[2]), "=r"(r[3]) : "r"(addr));
}
__device__ __forceinline__ void mma16816(float* c, const uint32_t* a, uint32_t b0, uint32_t b1) {
    asm volatile("mma.sync.aligned.m16n8k16.row.col.f32.bf16.bf16.f32 "
                 "{%0,%1,%2,%3}, {%4,%5,%6,%7}, {%8,%9}, {%0,%1,%2,%3};"
                 : "+f"(c[0]), "+f"(c[1]), "+f"(c[2]), "+f"(c[3])
                 : "r"(a[0]), "r"(a[1]), "r"(a[2]), "r"(a[3]), "r"(b0), "r"(b1));
}

// load a 128x64 fp32 tile, split into bf16 hi/lo, store to padded smem
__device__ __forceinline__ void load_split(const float* __restrict__ src, int row0, int kc,
                                           char* hi, char* lo, int tid) {
    #pragma unroll
    for (int i = 0; i < 8; i++) {
        int f   = i*256 + tid;        // 0..2047 float4s
        int row = f >> 4;             // 16 float4 per 64-col row
        int c4  = (f & 15) << 2;
        float4 v = *(const float4*)&src[(size_t)(row0 + row)*HD + kc + c4];
        __nv_bfloat16 hx = __float2bfloat16_rn(v.x);
        __nv_bfloat16 hy = __float2bfloat16_rn(v.y);
        __nv_bfloat16 hz = __float2bfloat16_rn(v.z);
        __nv_bfloat16 hw = __float2bfloat16_rn(v.w);
        float lx = v.x - __bfloat162float(hx);
        float ly = v.y - __bfloat162float(hy);
        float lz = v.z - __bfloat162float(hz);
        float lw = v.w - __bfloat162float(hw);
        uint2 hp, lp;
        hp.x = ((uint32_t)__bfloat16_as_ushort(hy) << 16) | __bfloat16_as_ushort(hx);
        hp.y = ((uint32_t)__bfloat16_as_ushort(hw) << 16) | __bfloat16_as_ushort(hz);
        lp.x = ((uint32_t)__bfloat16_as_ushort(__float2bfloat16_rn(ly)) << 16)
             |  __bfloat16_as_ushort(__float2bfloat16_rn(lx));
        lp.y = ((uint32_t)__bfloat16_as_ushort(__float2bfloat16_rn(lw)) << 16)
             |  __bfloat16_as_ushort(__float2bfloat16_rn(lz));
        int off = row*(SSTRIDE*2) + c4*2;   // bytes
        *(uint2*)(hi + off) = hp;
        *(uint2*)(lo + off) = lp;
    }
}

__global__ void __launch_bounds__(256, 1)
conv_mma_kernel(const float* __restrict__ A1, const float* __restrict__ A2,
                const float* __restrict__ W1, const float* __restrict__ W2,
                const float* __restrict__ bias, float* __restrict__ out) {
    extern __shared__ char smem[];
    char* pAh = smem;
    char* pAl = smem + TILE_B;
    char* pBh = smem + 2*TILE_B;
    char* pBl = smem + 3*TILE_B;
    uint32_t sbase;
    asm("{ .reg .u64 t; cvta.to.shared.u64 t, %1; cvt.u32.u64 %0, t; }" : "=r"(sbase) : "l"(smem));
    uint32_t aAh = sbase, aAl = sbase + TILE_B, aBh = sbase + 2*TILE_B, aBl = sbase + 3*TILE_B;

    int tid  = threadIdx.x;
    int wid  = tid >> 5;
    int lane = tid & 31;
    int wm   = wid >> 2;      // 0..1  -> warp covers rows wm*64..+63
    int wn   = wid & 3;       // 0..3  -> warp covers cols wn*32..+31
    int mblk = blockIdx.x * 128;

    float c[4][4][4];
    #pragma unroll
    for (int mt = 0; mt < 4; mt++)
        #pragma unroll
        for (int nt = 0; nt < 4; nt++)
            #pragma unroll
            for (int j = 0; j < 4; j++) c[mt][nt][j] = 0.f;

    int lr = lane & 15;            // ldmatrix row within 16
    int lc = (lane >> 4) * 8;      // k-half (0 or 8)

    #pragma unroll 1
    for (int ph = 0; ph < 2; ph++) {
        const float* A = ph ? A2 : A1;
        const float* W = ph ? W2 : W1;
        #pragma unroll 1
        for (int kc = 0; kc < 128; kc += KC) {
            __syncthreads();
            load_split(A, mblk, kc, pAh, pAl, tid);
            load_split(W, 0,    kc, pBh, pBl, tid);
            __syncthreads();
            #pragma unroll
            for (int ks = 0; ks < KC/16; ks++) {
                int k0 = ks*16;
                uint32_t ah[4][4], al[4][4], bh[2][4], bl[2][4];
                #pragma unroll
                for (int mt = 0; mt < 4; mt++) {
                    uint32_t ro = (uint32_t)((wm*64 + mt*16 + lr)*(SSTRIDE*2) + (k0 + lc)*2);
                    ldsm4(ah[mt], aAh + ro);
                    ldsm4(al[mt], aAl + ro);
                }
                #pragma unroll
                for (int h = 0; h < 2; h++) {
                    uint32_t ro = (uint32_t)((wn*32 + h*16 + lr)*(SSTRIDE*2) + (k0 + lc)*2);
                    ldsm4(bh[h], aBh + ro);   // NON-trans: W is [n][k] k-contiguous
                    ldsm4(bl[h], aBl + ro);
                }
                #pragma unroll
                for (int mt = 0; mt < 4; mt++) {
                    #pragma unroll
                    for (int nt = 0; nt < 4; nt++) {
                        int h = nt >> 1, o = nt & 1;
                        // Ah*Bh + Ah*Bl + Al*Bh
                        mma16816(c[mt][nt], ah[mt], bh[h][o], bh[h][o+2]);
                        mma16816(c[mt][nt], ah[mt], bl[h][o], bl[h][o+2]);
                        mma16816(c[mt][nt], al[mt], bh[h][o], bh[h][o+2]);
                    }
                }
            }
        }
    }

    // epilogue: bias + relu, c-frag: rows l/4 and l/4+8, cols (l%4)*2 + {0,1}
    int cr = lane >> 2;
    int cc = (lane & 3) * 2;
    #pragma unroll
    for (int mt = 0; mt < 4; mt++) {
        #pragma unroll
        for (int nt = 0; nt < 4; nt++) {
            int col = wn*32 + nt*8 + cc;
            float b0 = __ldg(&bias[col]);
            float b1 = __ldg(&bias[col+1]);
            int r0 = mblk + wm*64 + mt*16 + cr;
            float2 v0, v1;
            v0.x = fmaxf(c[mt][nt][0] + b0, 0.f);
            v0.y = fmaxf(c[mt][nt][1] + b1, 0.f);
            v1.x = fmaxf(c[mt][nt][2] + b0, 0.f);
            v1.y = fmaxf(c[mt][nt][3] + b1, 0.f);
            *(float2*)&out[(size_t)r0*HD + col]     = v0;
            *(float2*)&out[(size_t)(r0+8)*HD + col] = v1;
        }
    }
}

// ---------------- global mean pool into concat buffer ----------------
__global__ void meanpool_kernel(const float* __restrict__ x, float* __restrict__ cat,
                                int nodes, int off, float inv) {
    int g = blockIdx.x;
    int t = threadIdx.x;          // 512 threads
    int f = t & 127;
    int part = t >> 7;            // 0..3
    float acc = 0.f;
    size_t base = (size_t)g * nodes * HD;
    for (int i = part; i < nodes; i += 4)
        acc += x[base + (size_t)i*HD + f];
    __shared__ float s[512];
    s[t] = acc;
    __syncthreads();
    if (part == 0)
        cat[g*384 + off + f] = (s[f] + s[128+f] + s[256+f] + s[384+f]) * inv;
}

// ---------------- TopK scoring: warp per node ----------------
__global__ void score_kernel(const float* __restrict__ x, const float* __restrict__ pw,
                             float* __restrict__ score, int n) {
    int warp = (blockIdx.x*blockDim.x + threadIdx.x) >> 5;
    int lane = threadIdx.x & 31;
    if (warp >= n) return;
    float4 v = ((const float4*)x)[warp*32 + lane];
    float4 p = ((const float4*)pw)[lane];
    float d  = v.x*p.x + v.y*p.y + v.z*p.z + v.w*p.w;
    float pp = p.x*p.x + p.y*p.y + p.z*p.z + p.w*p.w;
    #pragma unroll
    for (int o = 16; o; o >>= 1) {
        d  += __shfl_xor_sync(0xFFFFFFFFu, d,  o);
        pp += __shfl_xor_sync(0xFFFFFFFFu, pp, o);
    }
    if (lane == 0) score[warp] = tanhf(d / sqrtf(pp));
}

// ---------------- TopK selection: one block per graph, bitonic sort 1024 ----------------
__global__ void topk_kernel(const float* __restrict__ score, int* __restrict__ map,
                            int* __restrict__ oldidx, float* __restrict__ val) {
    int g = blockIdx.x, t = threadIdx.x;   // 1024 threads
    __shared__ float sk[1024];
    __shared__ int   si[1024];
    map[g*NPER + t] = -1;
    sk[t] = score[g*NPER + t];
    si[t] = t;
    __syncthreads();
    for (int k = 2; k <= 1024; k <<= 1) {
        for (int j = k >> 1; j > 0; j >>= 1) {
            int ixj = t ^ j;
            if (ixj > t) {
                bool desc = ((t & k) == 0);
                float a = sk[t], b = sk[ixj];
                bool sw = desc ? (a < b) : (a > b);
                if (sw) {
                    sk[t] = b; sk[ixj] = a;
                    int tmp = si[t]; si[t] = si[ixj]; si[ixj] = tmp;
                }
            }
            __syncthreads();
        }
    }
    if (t < KKEEP) {
        int old = g*NPER + si[t];
        int nw  = g*KKEEP + t;
        map[old]   = nw;
        oldidx[nw] = old;
        val[nw]    = sk[t];
    }
}

// gather kept nodes, scale by score
__global__ void gather_scale_kernel(const float* __restrict__ x, const int* __restrict__ oldidx,
                                    const float* __restrict__ val, float* __restrict__ xp) {
    int warp = (blockIdx.x*blockDim.x + threadIdx.x) >> 5;
    int lane = threadIdx.x & 31;
    if (warp >= NPOOL) return;
    int old = oldidx[warp];
    float v = val[warp];
    float4 r = ((const float4*)x)[old*32 + lane];
    r.x *= v; r.y *= v; r.z *= v; r.w *= v;
    ((float4*)xp)[warp*32 + lane] = r;
}

// relabel edges through map, histogram valid edges by new dst
__global__ void filter_kernel(const int* __restrict__ src, const int* __restrict__ dst,
                              const int* __restrict__ map, int* __restrict__ ns,
                              int* __restrict__ nd, int* cnt2, int n) {
    int i = blockIdx.x*blockDim.x + threadIdx.x;
    if (i >= n) return;
    int a = map[src[i]];
    int b = map[dst[i]];
    if (a >= 0 && b >= 0) {
        ns[i] = a; nd[i] = b;
        atomicAdd(&cnt2[b], 1);
    } else {
        ns[i] = -1; nd[i] = 0;
    }
}

__global__ void scatter2_kernel(const int* __restrict__ ns, const int* __restrict__ nd,
                                int* cursor, int* __restrict__ csr, int n) {
    int i = blockIdx.x*blockDim.x + threadIdx.x;
    if (i < n && ns[i] >= 0) {
        int pos = atomicAdd(&cursor[nd[i]], 1);
        csr[pos] = ns[i];
    }
}

// ---------------- MLP head + log_softmax: one block per graph ----------------
__global__ void head_kernel(const float* __restrict__ cat, const float* __restrict__ W1,
                            const float* __restrict__ b1, const float* __restrict__ W2,
                            const float* __restrict__ b2, float* __restrict__ out) {
    int g = blockIdx.x, t = threadIdx.x;   // 128 threads
    __shared__ float sc[384];
    __shared__ float sh[128];
    __shared__ float sl[10];
    for (int i = t; i < 384; i += 128) sc[i] = cat[g*384 + i];
    __syncthreads();
    float acc = b1[t];
    #pragma unroll 4
    for (int k = 0; k < 384; k++) acc += sc[k] * W1[t*384 + k];
    sh[t] = fmaxf(acc, 0.f);
    __syncthreads();
    if (t < 10) {
        float a = b2[t];
        #pragma unroll 4
        for (int f = 0; f < 128; f++) a += sh[f] * W2[t*128 + f];
        sl[t] = a;
    }
    __syncthreads();
    if (t == 0) {
        float mx = sl[0];
        #pragma unroll
        for (int c = 1; c < 10; c++) mx = fmaxf(mx, sl[c]);
        float s = 0.f;
        #pragma unroll
        for (int c = 0; c < 10; c++) s += expf(sl[c] - mx);
        float lse = mx + logf(s);
        #pragma unroll
        for (int c = 0; c < 10; c++) out[g*10 + c] = sl[c] - lse;
    }
}

// ---------------- launch ----------------
extern "C" void kernel_launch(void* const* d_in, const int* in_sizes, int n_in,
                              void* d_out, int out_size) {
    const float* x       = (const float*)d_in[0];
    const int*   ei      = (const int*)  d_in[1];
    const int*   src     = ei;
    const int*   dst     = ei + NE;
    const float* W_rel1  = (const float*)d_in[3];
    const float* b_rel1  = (const float*)d_in[4];
    const float* W_root1 = (const float*)d_in[5];
    const float* W_rel2  = (const float*)d_in[6];
    const float* b_rel2  = (const float*)d_in[7];
    const float* W_root2 = (const float*)d_in[8];
    const float* W_rel3  = (const float*)d_in[9];
    const float* b_rel3  = (const float*)d_in[10];
    const float* W_root3 = (const float*)d_in[11];
    const float* p_w     = (const float*)d_in[12];
    const float* W_l1    = (const float*)d_in[13];
    const float* b_l1    = (const float*)d_in[14];
    const float* W_l2    = (const float*)d_in[15];
    const float* b_l2    = (const float*)d_in[16];
    float* out = (float*)d_out;

    float *agg, *x1, *x2, *xp, *val, *score, *cat;
    int *cnt, *rowptr, *cursor, *csr, *cnt2, *rowptr2, *cursor2, *csr2;
    int *ns, *nd, *map, *old, *bsum;
    cudaGetSymbolAddress((void**)&agg,     g_agg);
    cudaGetSymbolAddress((void**)&x1,      g_x1);
    cudaGetSymbolAddress((void**)&x2,      g_x2);
    cudaGetSymbolAddress((void**)&xp,      g_xp);
    cudaGetSymbolAddress((void**)&cnt,     g_cnt);
    cudaGetSymbolAddress((void**)&rowptr,  g_rowptr);
    cudaGetSymbolAddress((void**)&cursor,  g_cursor);
    cudaGetSymbolAddress((void**)&csr,     g_csr);
    cudaGetSymbolAddress((void**)&cnt2,    g_cnt2);
    cudaGetSymbolAddress((void**)&rowptr2, g_rowptr2);
    cudaGetSymbolAddress((void**)&cursor2, g_cursor2);
    cudaGetSymbolAddress((void**)&csr2,    g_csr2);
    cudaGetSymbolAddress((void**)&ns,      g_ns);
    cudaGetSymbolAddress((void**)&nd,      g_nd);
    cudaGetSymbolAddress((void**)&map,     g_map);
    cudaGetSymbolAddress((void**)&old,     g_old);
    cudaGetSymbolAddress((void**)&val,     g_val);
    cudaGetSymbolAddress((void**)&score,   g_score);
    cudaGetSymbolAddress((void**)&cat,     g_cat);
    cudaGetSymbolAddress((void**)&bsum,    g_bsum);

    cudaFuncSetAttribute(conv_mma_kernel, cudaFuncAttributeMaxDynamicSharedMemorySize,
                         CONV_SMEM);

    const int T = 256;
    // ---- CSR of original graph (by dst) ----
    zero_int_kernel<<<(NNODES+T-1)/T, T>>>(cnt, NNODES);
    hist_kernel<<<(NE+T-1)/T, T>>>(dst, cnt, NE);
    scan_local_kernel<<<(NNODES+1023)/1024, 1024>>>(cnt, rowptr, bsum, NNODES);
    scan_bsum_kernel<<<1, 64>>>(bsum, (NNODES+1023)/1024, rowptr, cursor);
    scan_add_kernel<<<(NNODES+T-1)/T, T>>>(rowptr, bsum, cursor, NNODES);
    scatter_kernel<<<(NE+T-1)/T, T>>>(src, dst, cursor, csr, NE);

    // ---- conv1 ----
    aggregate_kernel<<<NNODES/8, T>>>(x, rowptr, csr, agg, NNODES);
    conv_mma_kernel<<<NNODES/128, 256, CONV_SMEM>>>(agg, x, W_rel1, W_root1, b_rel1, x1);
    meanpool_kernel<<<NGRAPH, 512>>>(x1, cat, NPER, 0, 1.f/(float)NPER);

    // ---- conv2 ----
    aggregate_kernel<<<NNODES/8, T>>>(x1, rowptr, csr, agg, NNODES);
    conv_mma_kernel<<<NNODES/128, 256, CONV_SMEM>>>(agg, x1, W_rel2, W_root2, b_rel2, x2);
    meanpool_kernel<<<NGRAPH, 512>>>(x2, cat, NPER, 128, 1.f/(float)NPER);

    // ---- TopK pooling ----
    score_kernel<<<NNODES/8, T>>>(x2, p_w, score, NNODES);
    topk_kernel<<<NGRAPH, 1024>>>(score, map, old, val);
    gather_scale_kernel<<<NPOOL/8, T>>>(x2, old, val, xp);

    // ---- CSR of pooled graph ----
    zero_int_kernel<<<(NPOOL+T-1)/T, T>>>(cnt2, NPOOL);
    filter_kernel<<<(NE+T-1)/T, T>>>(src, dst, map, ns, nd, cnt2, NE);
    scan_local_kernel<<<(NPOOL+1023)/1024, 1024>>>(cnt2, rowptr2, bsum, NPOOL);
    scan_bsum_kernel<<<1, 64>>>(bsum, (NPOOL+1023)/1024, rowptr2, cursor2);
    scan_add_kernel<<<(NPOOL+T-1)/T, T>>>(rowptr2, bsum, cursor2, NPOOL);
    scatter2_kernel<<<(NE+T-1)/T, T>>>(ns, nd, cursor2, csr2, NE);

    // ---- conv3 (reuse x1 buffer as x3) ----
    aggregate_kernel<<<NPOOL/8, T>>>(xp, rowptr2, csr2, agg, NPOOL);
    conv_mma_kernel<<<NPOOL/128, 256, CONV_SMEM>>>(agg, xp, W_rel3, W_root3, b_rel3, x1);
    meanpool_kernel<<<NGRAPH, 512>>>(x1, cat, KKEEP, 256, 1.f/(float)KKEEP);

    // ---- head ----
    head_kernel<<<NGRAPH, 128>>>(cat, W_l1, b_l1, W_l2, b_l2, out);
}

// round 6
// speedup vs baseline: 1.9195x; 1.0331x over previous
#include <cuda_runtime.h>
#include <cuda_bf16.h>
#include <math.h>
#include <stdint.h>

// ---------------- problem constants ----------------
#define NGRAPH 64
#define NPER   1024
#define NNODES (NGRAPH*NPER)     // 65536
#define KKEEP  820
#define NPOOL  (NGRAPH*KKEEP)    // 52480
#define NE     524288
#define HD     128               // F == H == 128
#define CAP    48                // fixed CSR row capacity (Poisson(8) tail ~1e-18)

// ---------------- device scratch (no allocations allowed) ----------------
__device__ float g_x1 [NNODES*HD];   // fp32 activations (also x3)
__device__ float g_x2 [NNODES*HD];
__device__ float g_xp [NPOOL*HD];
// bf16 hi/lo split buffers
__device__ __nv_bfloat16 g_s0h[NNODES*HD], g_s0l[NNODES*HD];  // x split, then x2 split
__device__ __nv_bfloat16 g_s1h[NNODES*HD], g_s1l[NNODES*HD];  // x1 split, then xp split
__device__ __nv_bfloat16 g_agh[NNODES*HD], g_agl[NNODES*HD];  // aggregate split
__device__ __nv_bfloat16 g_wh[3*128*256], g_wl[3*128*256];    // fused [rel|root] weights
__device__ int   g_cnt    [NNODES];
__device__ int   g_csr    [NNODES*CAP];
__device__ int   g_cnt2   [NPOOL];
__device__ int   g_csr2   [NPOOL*CAP];
__device__ int   g_map    [NNODES];
__device__ int   g_old    [NPOOL];
__device__ float g_val    [NPOOL];
__device__ float g_score  [NNODES];
__device__ float g_cat    [NGRAPH*384];

// ---------------- helpers ----------------
__device__ __forceinline__ void split1(float v, __nv_bfloat16& h, __nv_bfloat16& l) {
    h = __float2bfloat16_rn(v);
    l = __float2bfloat16_rn(v - __bfloat162float(h));
}

// ---------------- tiny utility kernels ----------------
__global__ void zero_int_kernel(int* p, int n) {
    int i = blockIdx.x*blockDim.x + threadIdx.x;
    if (i < n) p[i] = 0;
}

// split x into bf16 hi/lo
__global__ void split_x_kernel(const float* __restrict__ x,
                               __nv_bfloat16* __restrict__ xh,
                               __nv_bfloat16* __restrict__ xl, int n4) {
    int i = blockIdx.x*blockDim.x + threadIdx.x;
    if (i >= n4) return;
    float4 v = ((const float4*)x)[i];
    __nv_bfloat16 h0,h1,h2,h3,l0,l1,l2,l3;
    split1(v.x,h0,l0); split1(v.y,h1,l1); split1(v.z,h2,l2); split1(v.w,h3,l3);
    ushort4 hp = make_ushort4(__bfloat16_as_ushort(h0), __bfloat16_as_ushort(h1),
                              __bfloat16_as_ushort(h2), __bfloat16_as_ushort(h3));
    ushort4 lp = make_ushort4(__bfloat16_as_ushort(l0), __bfloat16_as_ushort(l1),
                              __bfloat16_as_ushort(l2), __bfloat16_as_ushort(l3));
    ((ushort4*)xh)[i] = hp;
    ((ushort4*)xl)[i] = lp;
}

// build fused [rel | root] weight splits: Wf[conv][n][k], k<128 -> rel, else root
__global__ void split_w_kernel(const float* __restrict__ r1, const float* __restrict__ o1,
                               const float* __restrict__ r2, const float* __restrict__ o2,
                               const float* __restrict__ r3, const float* __restrict__ o3,
                               __nv_bfloat16* __restrict__ wh, __nv_bfloat16* __restrict__ wl) {
    int idx = blockIdx.x*blockDim.x + threadIdx.x;   // 3*128*256
    if (idx >= 3*128*256) return;
    int conv = idx >> 15;
    int rem  = idx & 32767;
    int n = rem >> 8, k = rem & 255;
    const float* rel  = (conv==0) ? r1 : (conv==1) ? r2 : r3;
    const float* root = (conv==0) ? o1 : (conv==1) ? o2 : o3;
    float v = (k < 128) ? rel[n*128 + k] : root[n*128 + (k-128)];
    __nv_bfloat16 h, l;
    split1(v, h, l);
    wh[idx] = h; wl[idx] = l;
}

// scatter edges into fixed-stride CSR slots (by dst)
__global__ void scatter_direct_kernel(const int* __restrict__ src, const int* __restrict__ dst,
                                      int* cnt, int* __restrict__ csr, int n) {
    int i = blockIdx.x*blockDim.x + threadIdx.x;
    if (i < n) {
        int d = dst[i];
        int slot = atomicAdd(&cnt[d], 1);
        if (slot < CAP) csr[d*CAP + slot] = src[i];
    }
}

// relabel + scatter pooled edges in one pass
__global__ void filter_direct_kernel(const int* __restrict__ src, const int* __restrict__ dst,
                                     const int* __restrict__ map, int* cnt2,
                                     int* __restrict__ csr2, int n) {
    int i = blockIdx.x*blockDim.x + threadIdx.x;
    if (i >= n) return;
    int a = map[src[i]];
    int b = map[dst[i]];
    if (a >= 0 && b >= 0) {
        int slot = atomicAdd(&cnt2[b], 1);
        if (slot < CAP) csr2[b*CAP + slot] = a;
    }
}

// ---------------- mean aggregation: warp per node, emits bf16 hi/lo ----------------
__global__ void aggregate_kernel(const float* __restrict__ x, const int* __restrict__ cnt,
                                 const int* __restrict__ csr,
                                 __nv_bfloat16* __restrict__ aggh,
                                 __nv_bfloat16* __restrict__ aggl, int n) {
    int warp = (blockIdx.x*blockDim.x + threadIdx.x) >> 5;
    int lane = threadIdx.x & 31;
    if (warp >= n) return;
    int deg = cnt[warp];
    const int* row = csr + (size_t)warp*CAP;
    float4 acc = make_float4(0.f, 0.f, 0.f, 0.f);
    const float4* x4 = (const float4*)x;
    for (int e = 0; e < deg; e++) {
        int s = row[e];
        float4 v = x4[s*32 + lane];
        acc.x += v.x; acc.y += v.y; acc.z += v.z; acc.w += v.w;
    }
    float inv = (deg > 0) ? 1.f/(float)deg : 0.f;
    acc.x *= inv; acc.y *= inv; acc.z *= inv; acc.w *= inv;
    __nv_bfloat16 h0,h1,h2,h3,l0,l1,l2,l3;
    split1(acc.x,h0,l0); split1(acc.y,h1,l1); split1(acc.z,h2,l2); split1(acc.w,h3,l3);
    ushort4 hp = make_ushort4(__bfloat16_as_ushort(h0), __bfloat16_as_ushort(h1),
                              __bfloat16_as_ushort(h2), __bfloat16_as_ushort(h3));
    ushort4 lp = make_ushort4(__bfloat16_as_ushort(l0), __bfloat16_as_ushort(l1),
                              __bfloat16_as_ushort(l2), __bfloat16_as_ushort(l3));
    ((ushort4*)aggh)[warp*32 + lane] = hp;
    ((ushort4*)aggl)[warp*32 + lane] = lp;
}

// =======================================================================
//   bf16x3 mma.sync fused GraphConv GEMM, cp.async double-buffered
//   out = relu( [A1 A2] · Wf.T + bias ),  Wf = [rel | root]  (K=256)
//   chunk c in 0..3: A = (c<2 ? A1 : A2) cols (c&1)*64, Wf cols c*64
// =======================================================================

#define SSTRIDE  72                      // bf16 per smem row (64+8 pad)
#define MAT_B    (128*SSTRIDE*2)         // 18432 bytes
#define BUF_B    (4*MAT_B)               // Ah, Al, Wh, Wl
#define CONV_SMEM (2*BUF_B)              // double buffer = 147456

__device__ __forceinline__ void ldsm4(uint32_t* r, uint32_t addr) {
    asm volatile("ldmatrix.sync.aligned.m8n8.x4.shared.b16 {%0,%1,%2,%3}, [%4];"
                 : "=r"(r[0]), "=r"(r[1]), "=r"(r[2]), "=r"(r[3]) : "r"(addr));
}
__device__ __forceinline__ void mma16816(float* c, const uint32_t* a, uint32_t b0, uint32_t b1) {
    asm volatile("mma.sync.aligned.m16n8k16.row.col.f32.bf16.bf16.f32 "
                 "{%0,%1,%2,%3}, {%4,%5,%6,%7}, {%8,%9}, {%0,%1,%2,%3};"
                 : "+f"(c[0]), "+f"(c[1]), "+f"(c[2]), "+f"(c[3])
                 : "r"(a[0]), "r"(a[1]), "r"(a[2]), "r"(a[3]), "r"(b0), "r"(b1));
}
__device__ __forceinline__ void cpasync16(uint32_t saddr, const void* g) {
    asm volatile("cp.async.cg.shared.global [%0], [%1], 16;" :: "r"(saddr), "l"(g));
}

__global__ void __launch_bounds__(256, 1)
conv_mma_kernel(const __nv_bfloat16* __restrict__ A1h, const __nv_bfloat16* __restrict__ A1l,
                const __nv_bfloat16* __restrict__ A2h, const __nv_bfloat16* __restrict__ A2l,
                const __nv_bfloat16* __restrict__ Wh,  const __nv_bfloat16* __restrict__ Wl,
                const float* __restrict__ bias, float* __restrict__ out,
                __nv_bfloat16* __restrict__ outh, __nv_bfloat16* __restrict__ outl,
                int writeSplit) {
    extern __shared__ char smem[];
    uint32_t sbase;
    asm("{ .reg .u64 t; cvta.to.shared.u64 t, %1; cvt.u32.u64 %0, t; }" : "=r"(sbase) : "l"(smem));

    int tid  = threadIdx.x;
    int wid  = tid >> 5;
    int lane = tid & 31;
    int wm   = wid >> 2;      // 0..1
    int wn   = wid & 3;       // 0..3
    int mblk = blockIdx.x * 128;

    const __nv_bfloat16* Ah_src[2] = {A1h, A2h};
    const __nv_bfloat16* Al_src[2] = {A1l, A2l};

    // issue cp.async for chunk c into buffer b
    auto issue = [&](int c, int b) {
        uint32_t base = sbase + (uint32_t)b*BUF_B;
        const __nv_bfloat16* ah = Ah_src[c>>1];
        const __nv_bfloat16* al = Al_src[c>>1];
        int kcA = (c & 1) * 64;
        int kcW = c * 64;
        #pragma unroll
        for (int i = 0; i < 4; i++) {
            int seg = i*256 + tid;          // 0..1023
            int row = seg >> 3;
            int c8  = (seg & 7) * 8;
            uint32_t soff = (uint32_t)(row*(SSTRIDE*2) + c8*2);
            cpasync16(base + 0*MAT_B + soff, ah + (size_t)(mblk+row)*HD + kcA + c8);
            cpasync16(base + 1*MAT_B + soff, al + (size_t)(mblk+row)*HD + kcA + c8);
            cpasync16(base + 2*MAT_B + soff, Wh + (size_t)row*256 + kcW + c8);
            cpasync16(base + 3*MAT_B + soff, Wl + (size_t)row*256 + kcW + c8);
        }
    };

    float c[4][4][4];
    #pragma unroll
    for (int mt = 0; mt < 4; mt++)
        #pragma unroll
        for (int nt = 0; nt < 4; nt++)
            #pragma unroll
            for (int j = 0; j < 4; j++) c[mt][nt][j] = 0.f;

    int lr = lane & 15;
    int lc = (lane >> 4) * 8;

    issue(0, 0);
    asm volatile("cp.async.commit_group;");

    #pragma unroll 1
    for (int ch = 0; ch < 4; ch++) {
        int b = ch & 1;
        if (ch < 3) {
            issue(ch+1, (ch+1) & 1);
            asm volatile("cp.async.commit_group;");
            asm volatile("cp.async.wait_group 1;");
        } else {
            asm volatile("cp.async.wait_group 0;");
        }
        __syncthreads();
        uint32_t aAh = sbase + (uint32_t)b*BUF_B;
        uint32_t aAl = aAh + MAT_B;
        uint32_t aBh = aAh + 2*MAT_B;
        uint32_t aBl = aAh + 3*MAT_B;
        #pragma unroll
        for (int ks = 0; ks < 4; ks++) {
            int k0 = ks*16;
            uint32_t ah[4][4], al[4][4], bh[2][4], bl[2][4];
            #pragma unroll
            for (int mt = 0; mt < 4; mt++) {
                uint32_t ro = (uint32_t)((wm*64 + mt*16 + lr)*(SSTRIDE*2) + (k0 + lc)*2);
                ldsm4(ah[mt], aAh + ro);
                ldsm4(al[mt], aAl + ro);
            }
            #pragma unroll
            for (int h = 0; h < 2; h++) {
                uint32_t ro = (uint32_t)((wn*32 + h*16 + lr)*(SSTRIDE*2) + (k0 + lc)*2);
                ldsm4(bh[h], aBh + ro);
                ldsm4(bl[h], aBl + ro);
            }
            #pragma unroll
            for (int mt = 0; mt < 4; mt++) {
                #pragma unroll
                for (int nt = 0; nt < 4; nt++) {
                    int h = nt >> 1, o = nt & 1;
                    mma16816(c[mt][nt], ah[mt], bh[h][o], bh[h][o+2]);
                    mma16816(c[mt][nt], ah[mt], bl[h][o], bl[h][o+2]);
                    mma16816(c[mt][nt], al[mt], bh[h][o], bh[h][o+2]);
                }
            }
        }
        __syncthreads();
    }

    // epilogue: bias + relu (+ optional bf16 split for next layer)
    int cr = lane >> 2;
    int cc = (lane & 3) * 2;
    #pragma unroll
    for (int mt = 0; mt < 4; mt++) {
        #pragma unroll
        for (int nt = 0; nt < 4; nt++) {
            int col = wn*32 + nt*8 + cc;
            float b0 = __ldg(&bias[col]);
            float b1 = __ldg(&bias[col+1]);
            int r0 = mblk + wm*64 + mt*16 + cr;
            float2 v0, v1;
            v0.x = fmaxf(c[mt][nt][0] + b0, 0.f);
            v0.y = fmaxf(c[mt][nt][1] + b1, 0.f);
            v1.x = fmaxf(c[mt][nt][2] + b0, 0.f);
            v1.y = fmaxf(c[mt][nt][3] + b1, 0.f);
            *(float2*)&out[(size_t)r0*HD + col]     = v0;
            *(float2*)&out[(size_t)(r0+8)*HD + col] = v1;
            if (writeSplit) {
                __nv_bfloat16 h0,h1,l0,l1;
                split1(v0.x,h0,l0); split1(v0.y,h1,l1);
                *(ushort2*)&outh[(size_t)r0*HD + col] =
                    make_ushort2(__bfloat16_as_ushort(h0), __bfloat16_as_ushort(h1));
                *(ushort2*)&outl[(size_t)r0*HD + col] =
                    make_ushort2(__bfloat16_as_ushort(l0), __bfloat16_as_ushort(l1));
                split1(v1.x,h0,l0); split1(v1.y,h1,l1);
                *(ushort2*)&outh[(size_t)(r0+8)*HD + col] =
                    make_ushort2(__bfloat16_as_ushort(h0), __bfloat16_as_ushort(h1));
                *(ushort2*)&outl[(size_t)(r0+8)*HD + col] =
                    make_ushort2(__bfloat16_as_ushort(l0), __bfloat16_as_ushort(l1));
            }
        }
    }
}

// ---------------- global mean pool into concat buffer ----------------
__global__ void meanpool_kernel(const float* __restrict__ x, float* __restrict__ cat,
                                int nodes, int off, float inv) {
    int g = blockIdx.x;
    int t = threadIdx.x;          // 512 threads
    int f = t & 127;
    int part = t >> 7;            // 0..3
    float acc = 0.f;
    size_t base = (size_t)g * nodes * HD;
    for (int i = part; i < nodes; i += 4)
        acc += x[base + (size_t)i*HD + f];
    __shared__ float s[512];
    s[t] = acc;
    __syncthreads();
    if (part == 0)
        cat[g*384 + off + f] = (s[f] + s[128+f] + s[256+f] + s[384+f]) * inv;
}

// ---------------- TopK scoring: warp per node ----------------
__global__ void score_kernel(const float* __restrict__ x, const float* __restrict__ pw,
                             float* __restrict__ score, int n) {
    int warp = (blockIdx.x*blockDim.x + threadIdx.x) >> 5;
    int lane = threadIdx.x & 31;
    if (warp >= n) return;
    float4 v = ((const float4*)x)[warp*32 + lane];
    float4 p = ((const float4*)pw)[lane];
    float d  = v.x*p.x + v.y*p.y + v.z*p.z + v.w*p.w;
    float pp = p.x*p.x + p.y*p.y + p.z*p.z + p.w*p.w;
    #pragma unroll
    for (int o = 16; o; o >>= 1) {
        d  += __shfl_xor_sync(0xFFFFFFFFu, d,  o);
        pp += __shfl_xor_sync(0xFFFFFFFFu, pp, o);
    }
    if (lane == 0) score[warp] = tanhf(d / sqrtf(pp));
}

// ---------------- TopK selection: one block per graph, bitonic sort 1024 ----------------
__global__ void topk_kernel(const float* __restrict__ score, int* __restrict__ map,
                            int* __restrict__ oldidx, float* __restrict__ val) {
    int g = blockIdx.x, t = threadIdx.x;   // 1024 threads
    __shared__ float sk[1024];
    __shared__ int   si[1024];
    map[g*NPER + t] = -1;
    sk[t] = score[g*NPER + t];
    si[t] = t;
    __syncthreads();
    for (int k = 2; k <= 1024; k <<= 1) {
        for (int j = k >> 1; j > 0; j >>= 1) {
            int ixj = t ^ j;
            if (ixj > t) {
                bool desc = ((t & k) == 0);
                float a = sk[t], b = sk[ixj];
                bool sw = desc ? (a < b) : (a > b);
                if (sw) {
                    sk[t] = b; sk[ixj] = a;
                    int tmp = si[t]; si[t] = si[ixj]; si[ixj] = tmp;
                }
            }
            __syncthreads();
        }
    }
    if (t < KKEEP) {
        int old = g*NPER + si[t];
        int nw  = g*KKEEP + t;
        map[old]   = nw;
        oldidx[nw] = old;
        val[nw]    = sk[t];
    }
}

// gather kept nodes, scale by score; emit fp32 and bf16 split
__global__ void gather_scale_kernel(const float* __restrict__ x, const int* __restrict__ oldidx,
                                    const float* __restrict__ val, float* __restrict__ xp,
                                    __nv_bfloat16* __restrict__ xph,
                                    __nv_bfloat16* __restrict__ xpl) {
    int warp = (blockIdx.x*blockDim.x + threadIdx.x) >> 5;
    int lane = threadIdx.x & 31;
    if (warp >= NPOOL) return;
    int old = oldidx[warp];
    float v = val[warp];
    float4 r = ((const float4*)x)[old*32 + lane];
    r.x *= v; r.y *= v; r.z *= v; r.w *= v;
    ((float4*)xp)[warp*32 + lane] = r;
    __nv_bfloat16 h0,h1,h2,h3,l0,l1,l2,l3;
    split1(r.x,h0,l0); split1(r.y,h1,l1); split1(r.z,h2,l2); split1(r.w,h3,l3);
    ((ushort4*)xph)[warp*32 + lane] =
        make_ushort4(__bfloat16_as_ushort(h0), __bfloat16_as_ushort(h1),
                     __bfloat16_as_ushort(h2), __bfloat16_as_ushort(h3));
    ((ushort4*)xpl)[warp*32 + lane] =
        make_ushort4(__bfloat16_as_ushort(l0), __bfloat16_as_ushort(l1),
                     __bfloat16_as_ushort(l2), __bfloat16_as_ushort(l3));
}

// ---------------- MLP head + log_softmax: one block per graph ----------------
__global__ void head_kernel(const float* __restrict__ cat, const float* __restrict__ W1,
                            const float* __restrict__ b1, const float* __restrict__ W2,
                            const float* __restrict__ b2, float* __restrict__ out) {
    int g = blockIdx.x, t = threadIdx.x;   // 128 threads
    __shared__ float sc[384];
    __shared__ float sh[128];
    __shared__ float sl[10];
    for (int i = t; i < 384; i += 128) sc[i] = cat[g*384 + i];
    __syncthreads();
    float acc = b1[t];
    #pragma unroll 4
    for (int k = 0; k < 384; k++) acc += sc[k] * W1[t*384 + k];
    sh[t] = fmaxf(acc, 0.f);
    __syncthreads();
    if (t < 10) {
        float a = b2[t];
        #pragma unroll 4
        for (int f = 0; f < 128; f++) a += sh[f] * W2[t*128 + f];
        sl[t] = a;
    }
    __syncthreads();
    if (t == 0) {
        float mx = sl[0];
        #pragma unroll
        for (int c = 1; c < 10; c++) mx = fmaxf(mx, sl[c]);
        float s = 0.f;
        #pragma unroll
        for (int c = 0; c < 10; c++) s += expf(sl[c] - mx);
        float lse = mx + logf(s);
        #pragma unroll
        for (int c = 0; c < 10; c++) out[g*10 + c] = sl[c] - lse;
    }
}

// ---------------- launch ----------------
extern "C" void kernel_launch(void* const* d_in, const int* in_sizes, int n_in,
                              void* d_out, int out_size) {
    const float* x       = (const float*)d_in[0];
    const int*   ei      = (const int*)  d_in[1];
    const int*   src     = ei;
    const int*   dst     = ei + NE;
    const float* W_rel1  = (const float*)d_in[3];
    const float* b_rel1  = (const float*)d_in[4];
    const float* W_root1 = (const float*)d_in[5];
    const float* W_rel2  = (const float*)d_in[6];
    const float* b_rel2  = (const float*)d_in[7];
    const float* W_root2 = (const float*)d_in[8];
    const float* W_rel3  = (const float*)d_in[9];
    const float* b_rel3  = (const float*)d_in[10];
    const float* W_root3 = (const float*)d_in[11];
    const float* p_w     = (const float*)d_in[12];
    const float* W_l1    = (const float*)d_in[13];
    const float* b_l1    = (const float*)d_in[14];
    const float* W_l2    = (const float*)d_in[15];
    const float* b_l2    = (const float*)d_in[16];
    float* out = (float*)d_out;

    float *x1, *x2, *xp, *val, *score, *cat;
    __nv_bfloat16 *s0h, *s0l, *s1h, *s1l, *agh, *agl, *wh, *wl;
    int *cnt, *csr, *cnt2, *csr2, *map, *old;
    cudaGetSymbolAddress((void**)&x1,   g_x1);
    cudaGetSymbolAddress((void**)&x2,   g_x2);
    cudaGetSymbolAddress((void**)&xp,   g_xp);
    cudaGetSymbolAddress((void**)&s0h,  g_s0h);
    cudaGetSymbolAddress((void**)&s0l,  g_s0l);
    cudaGetSymbolAddress((void**)&s1h,  g_s1h);
    cudaGetSymbolAddress((void**)&s1l,  g_s1l);
    cudaGetSymbolAddress((void**)&agh,  g_agh);
    cudaGetSymbolAddress((void**)&agl,  g_agl);
    cudaGetSymbolAddress((void**)&wh,   g_wh);
    cudaGetSymbolAddress((void**)&wl,   g_wl);
    cudaGetSymbolAddress((void**)&cnt,  g_cnt);
    cudaGetSymbolAddress((void**)&csr,  g_csr);
    cudaGetSymbolAddress((void**)&cnt2, g_cnt2);
    cudaGetSymbolAddress((void**)&csr2, g_csr2);
    cudaGetSymbolAddress((void**)&map,  g_map);
    cudaGetSymbolAddress((void**)&old,  g_old);
    cudaGetSymbolAddress((void**)&val,  g_val);
    cudaGetSymbolAddress((void**)&score,g_score);
    cudaGetSymbolAddress((void**)&cat,  g_cat);

    cudaFuncSetAttribute(conv_mma_kernel, cudaFuncAttributeMaxDynamicSharedMemorySize,
                         CONV_SMEM);

    const int T = 256;
    // ---- precompute splits + CSR ----
    split_x_kernel<<<(NNODES*HD/4 + T-1)/T, T>>>(x, s0h, s0l, NNODES*HD/4);
    split_w_kernel<<<(3*128*256 + T-1)/T, T>>>(W_rel1, W_root1, W_rel2, W_root2,
                                               W_rel3, W_root3, wh, wl);
    zero_int_kernel<<<(NNODES+T-1)/T, T>>>(cnt, NNODES);
    scatter_direct_kernel<<<(NE+T-1)/T, T>>>(src, dst, cnt, csr, NE);

    // ---- conv1 ----
    aggregate_kernel<<<NNODES/8, T>>>(x, cnt, csr, agh, agl, NNODES);
    conv_mma_kernel<<<NNODES/128, 256, CONV_SMEM>>>(agh, agl, s0h, s0l,
                                                    wh, wl, b_rel1, x1, s1h, s1l, 1);
    meanpool_kernel<<<NGRAPH, 512>>>(x1, cat, NPER, 0, 1.f/(float)NPER);

    // ---- conv2 (writes x2 split into s0) ----
    aggregate_kernel<<<NNODES/8, T>>>(x1, cnt, csr, agh, agl, NNODES);
    conv_mma_kernel<<<NNODES/128, 256, CONV_SMEM>>>(agh, agl, s1h, s1l,
                                                    wh + 128*256, wl + 128*256,
                                                    b_rel2, x2, s0h, s0l, 1);
    meanpool_kernel<<<NGRAPH, 512>>>(x2, cat, NPER, 128, 1.f/(float)NPER);

    // ---- TopK pooling (xp split into s1) ----
    score_kernel<<<NNODES/8, T>>>(x2, p_w, score, NNODES);
    topk_kernel<<<NGRAPH, 1024>>>(score, map, old, val);
    gather_scale_kernel<<<NPOOL/8, T>>>(x2, old, val, xp, s1h, s1l);

    // ---- pooled CSR ----
    zero_int_kernel<<<(NPOOL+T-1)/T, T>>>(cnt2, NPOOL);
    filter_direct_kernel<<<(NE+T-1)/T, T>>>(src, dst, map, cnt2, csr2, NE);

    // ---- conv3 (reuse x1 as x3; no split output needed) ----
    aggregate_kernel<<<NPOOL/8, T>>>(xp, cnt2, csr2, agh, agl, NPOOL);
    conv_mma_kernel<<<NPOOL/128, 256, CONV_SMEM>>>(agh, agl, s1h, s1l,
                                                   wh + 2*128*256, wl + 2*128*256,
                                                   b_rel3, x1, (__nv_bfloat16*)0,
                                                   (__nv_bfloat16*)0, 0);
    meanpool_kernel<<<NGRAPH, 512>>>(x1, cat, KKEEP, 256, 1.f/(float)KKEEP);

    // ---- head ----
    head_kernel<<<NGRAPH, 128>>>(cat, W_l1, b_l1, W_l2, b_l2, out);
}